// round 2
// baseline (speedup 1.0000x reference)
#include <cuda_runtime.h>
#include <cuda_bf16.h>
#include <cstdint>

// ---------------------------------------------------------------------------
// ConvMultiheadAttention: B=8, S=1024, D=512, H=8, hd=64, KERNEL=3
// out  = [8,1024,512]  ; ave = [8,1024,1024]
// ---------------------------------------------------------------------------

#define BB 8
#define SS 1024
#define DD 512
#define HH 8
#define HD 64
#define SC_LD 1032   // padded row stride for score tile

typedef unsigned long long ull;

// ----- f32x2 helpers (Blackwell packed fp32: 2 FMAs per instruction) -------
__device__ __forceinline__ ull f2fma(ull a, ull b, ull c) {
    ull d; asm("fma.rn.f32x2 %0, %1, %2, %3;" : "=l"(d) : "l"(a), "l"(b), "l"(c)); return d;
}
__device__ __forceinline__ ull f2dup(float x) {
    ull d; asm("mov.b64 %0, {%1, %1};" : "=l"(d) : "f"(x)); return d;
}
__device__ __forceinline__ ull f2add(ull a, ull b) {
    ull d; asm("add.rn.f32x2 %0, %1, %2;" : "=l"(d) : "l"(a), "l"(b)); return d;
}
__device__ __forceinline__ float2 f2unpk(ull a) {
    float2 r; asm("mov.b64 {%0, %1}, %2;" : "=f"(r.x), "=f"(r.y) : "l"(a)); return r;
}

// ----- scratch (static device globals) --------------------------------------
__device__ float g_xt[3][BB][DD][SS];    // transposed inputs  [B,D,S]
__device__ float g_qkv[3][BB][DD][SS];   // conv outputs Q,K,V [B,D,S]
__device__ float g_vt[BB][SS][DD];       // V transposed to [B,S,D]
__device__ float g_o1[BB][SS][DD];       // pre-projection output

// ---------------------------------------------------------------------------
// Kernel 1: transpose [B,S,D] -> [B,D,S] for q, k, v
// ---------------------------------------------------------------------------
__global__ void transpose_kernel(const float* __restrict__ q,
                                 const float* __restrict__ k,
                                 const float* __restrict__ v) {
    __shared__ float tile[32][33];
    int zz = blockIdx.z;
    int tn = zz / BB, b = zz % BB;
    const float* src = (tn == 0) ? q : (tn == 1) ? k : v;
    float* dst = &g_xt[tn][b][0][0];
    int s0 = blockIdx.x * 32, d0 = blockIdx.y * 32;
    int tx = threadIdx.x, ty = threadIdx.y;
    #pragma unroll
    for (int i = ty; i < 32; i += 8)
        tile[i][tx] = src[((size_t)b * SS + s0 + i) * DD + d0 + tx];
    __syncthreads();
    #pragma unroll
    for (int i = ty; i < 32; i += 8)
        dst[(size_t)(d0 + i) * SS + s0 + tx] = tile[tx][i];
}

// ---------------------------------------------------------------------------
// Kernel 2: conv1d projections as GEMM (double-buffered smem).
// ---------------------------------------------------------------------------
__global__ __launch_bounds__(256) void conv_kernel(
    const float* __restrict__ Wq, const float* __restrict__ bq,
    const float* __restrict__ Wk, const float* __restrict__ bk,
    const float* __restrict__ Wv, const float* __restrict__ bv) {
    int zz = blockIdx.z;
    int tn = zz / BB, b = zz % BB;
    const float* W    = (tn == 0) ? Wq : (tn == 1) ? Wk : Wv;
    const float* bias = (tn == 0) ? bq : (tn == 1) ? bk : bv;
    const int KER  = (tn == 2) ? 1 : 3;
    const int Kdim = DD * KER;
    const int pad  = KER >> 1;
    const float* xsrc = &g_xt[tn][b][0][0];
    float* out = &g_qkv[tn][b][0][0];

    __shared__ float As[2][8][128];
    __shared__ float Bs[2][8][128];

    const int tid = threadIdx.x;
    const int m0 = blockIdx.x * 128, n0 = blockIdx.y * 128;
    const int tx = tid & 15, ty = tid >> 4;
    const int ai = tid >> 1, aj = (tid & 1) * 4;
    const int bj = tid >> 5, bn = (tid & 31) * 4;

    ull acc[8][4];
    #pragma unroll
    for (int i = 0; i < 8; i++)
        #pragma unroll
        for (int p = 0; p < 4; p++) acc[i][p] = 0ULL;

    float4 wreg;
    float bv4[4];

    // prologue: load slab 0
    {
        wreg = *(const float4*)&W[(size_t)(m0 + ai) * Kdim + aj];
        int kk = bj;
        int ci, kof;
        if (KER == 3) { ci = kk / 3; kof = kk - ci * 3; }
        else          { ci = kk;     kof = 0; }
        const float* xr = xsrc + (size_t)ci * SS;
        #pragma unroll
        for (int u = 0; u < 4; u++) {
            int t = n0 + bn + u + kof - pad;
            bv4[u] = (t >= 0 && t < SS) ? xr[t] : 0.0f;
        }
        As[0][aj + 0][ai] = wreg.x; As[0][aj + 1][ai] = wreg.y;
        As[0][aj + 2][ai] = wreg.z; As[0][aj + 3][ai] = wreg.w;
        #pragma unroll
        for (int u = 0; u < 4; u++) Bs[0][bj][bn + u] = bv4[u];
    }
    __syncthreads();

    int cur = 0;
    for (int kk0 = 0; kk0 < Kdim; kk0 += 8) {
        bool hn = (kk0 + 8) < Kdim;
        if (hn) {
            wreg = *(const float4*)&W[(size_t)(m0 + ai) * Kdim + kk0 + 8 + aj];
            int kk = kk0 + 8 + bj;
            int ci, kof;
            if (KER == 3) { ci = kk / 3; kof = kk - ci * 3; }
            else          { ci = kk;     kof = 0; }
            const float* xr = xsrc + (size_t)ci * SS;
            #pragma unroll
            for (int u = 0; u < 4; u++) {
                int t = n0 + bn + u + kof - pad;
                bv4[u] = (t >= 0 && t < SS) ? xr[t] : 0.0f;
            }
        }

        #pragma unroll
        for (int j = 0; j < 8; j++) {
            float4 a0 = *(float4*)&As[cur][j][ty * 8];
            float4 a1 = *(float4*)&As[cur][j][ty * 8 + 4];
            ull b2[4];
            #pragma unroll
            for (int p = 0; p < 4; p++) b2[p] = *(ull*)&Bs[cur][j][tx * 8 + 2 * p];
            float av[8] = {a0.x, a0.y, a0.z, a0.w, a1.x, a1.y, a1.z, a1.w};
            #pragma unroll
            for (int i = 0; i < 8; i++) {
                ull ad = f2dup(av[i]);
                #pragma unroll
                for (int p = 0; p < 4; p++) acc[i][p] = f2fma(ad, b2[p], acc[i][p]);
            }
        }

        if (hn) {
            int nb = cur ^ 1;
            As[nb][aj + 0][ai] = wreg.x; As[nb][aj + 1][ai] = wreg.y;
            As[nb][aj + 2][ai] = wreg.z; As[nb][aj + 3][ai] = wreg.w;
            #pragma unroll
            for (int u = 0; u < 4; u++) Bs[nb][bj][bn + u] = bv4[u];
        }
        __syncthreads();
        cur ^= 1;
    }

    #pragma unroll
    for (int i = 0; i < 8; i++) {
        int m = m0 + ty * 8 + i;
        ull bb = f2dup(bias[m]);
        #pragma unroll
        for (int p = 0; p < 4; p++) {
            ull r = f2add(acc[i][p], bb);
            *(ull*)&out[(size_t)m * SS + n0 + tx * 8 + 2 * p] = r;
        }
    }
}

// ---------------------------------------------------------------------------
// Kernel 3: transpose V conv output [B,D,S] -> [B,S,D]
// ---------------------------------------------------------------------------
__global__ void vt_kernel() {
    __shared__ float tile[32][33];
    int b = blockIdx.z;
    const float* src = &g_qkv[2][b][0][0];
    float* dst = &g_vt[b][0][0];
    int s0 = blockIdx.x * 32, d0 = blockIdx.y * 32;
    int tx = threadIdx.x, ty = threadIdx.y;
    #pragma unroll
    for (int i = ty; i < 32; i += 8)
        tile[i][tx] = src[(size_t)(d0 + i) * SS + s0 + tx];
    __syncthreads();
    #pragma unroll
    for (int i = ty; i < 32; i += 8)
        dst[(size_t)(s0 + i) * DD + d0 + tx] = tile[tx][i];
}

// ---------------------------------------------------------------------------
// Kernel 4: fused attention. Per (b, 16-row s-tile): for each head:
// scores (f32x2 GEMM vs staged K slabs) -> softmax -> ave accumulation in
// smem -> PV (warp-split t-reduction vs staged transposed V) -> o1.
// P never touches HBM. ave written once at the end.
// ---------------------------------------------------------------------------
__global__ __launch_bounds__(256) void fused_attn(float* __restrict__ ave) {
    extern __shared__ float smp[];
    float* sc = smp;                       // [16][SC_LD]   16512 floats
    float* av = smp + 16 * SC_LD;          // [16][1024]    16384
    float* kv = av + 16 * 1024;            // max(32*516, 256*68) = 17408
    float* qt = kv + 17408;                // [64][16]      1024

    const int b = blockIdx.y, s0 = blockIdx.x * 16;
    const int tid = threadIdx.x;

    // zero ave accumulator
    #pragma unroll
    for (int i = 0; i < 16; i++)
        *(float4*)&av[i * 1024 + tid * 4] = make_float4(0.f, 0.f, 0.f, 0.f);

    const int tx = tid & 127, ty = tid >> 7;       // scores: 8 rows x 4 cols
    const int w = tid >> 5, lane = tid & 31;       // PV mapping
    const int r_l = (lane >> 3) * 4, d_l = (lane & 7) * 8;

    for (int h = 0; h < HH; h++) {
        const float* Qg = &g_qkv[0][b][h * HD][0];
        const float* Kg = &g_qkv[1][b][h * HD][0];

        __syncthreads();   // qt / kv / stage reuse from previous head

        // load Q tile [64 d][16 r]
        {
            int d = tid >> 2, rq = (tid & 3) * 4;
            *(float4*)&qt[d * 16 + rq] = *(const float4*)&Qg[(size_t)d * SS + s0 + rq];
        }

        // ---------------- scores ----------------
        for (int tch = 0; tch < 2; tch++) {
            ull acc[4][4];
            #pragma unroll
            for (int p = 0; p < 4; p++)
                #pragma unroll
                for (int j = 0; j < 4; j++) acc[p][j] = 0ULL;

            for (int dch = 0; dch < 2; dch++) {
                __syncthreads();
                #pragma unroll
                for (int i = 0; i < 16; i++) {
                    int e = i * 1024 + tid * 4;
                    int d = e >> 9, t = e & 511;
                    *(float4*)&kv[d * 516 + t] =
                        *(const float4*)&Kg[(size_t)(dch * 32 + d) * SS + tch * 512 + t];
                }
                __syncthreads();
                #pragma unroll
                for (int d = 0; d < 32; d++) {
                    const float* qr = &qt[(dch * 32 + d) * 16 + ty * 8];
                    ull q0 = *(ull*)&qr[0], q1 = *(ull*)&qr[2];
                    ull q2 = *(ull*)&qr[4], q3 = *(ull*)&qr[6];
                    float4 kf = *(float4*)&kv[d * 516 + tx * 4];
                    ull k0 = f2dup(kf.x), k1 = f2dup(kf.y);
                    ull k2 = f2dup(kf.z), k3 = f2dup(kf.w);
                    acc[0][0] = f2fma(q0, k0, acc[0][0]); acc[0][1] = f2fma(q0, k1, acc[0][1]);
                    acc[0][2] = f2fma(q0, k2, acc[0][2]); acc[0][3] = f2fma(q0, k3, acc[0][3]);
                    acc[1][0] = f2fma(q1, k0, acc[1][0]); acc[1][1] = f2fma(q1, k1, acc[1][1]);
                    acc[1][2] = f2fma(q1, k2, acc[1][2]); acc[1][3] = f2fma(q1, k3, acc[1][3]);
                    acc[2][0] = f2fma(q2, k0, acc[2][0]); acc[2][1] = f2fma(q2, k1, acc[2][1]);
                    acc[2][2] = f2fma(q2, k2, acc[2][2]); acc[2][3] = f2fma(q2, k3, acc[2][3]);
                    acc[3][0] = f2fma(q3, k0, acc[3][0]); acc[3][1] = f2fma(q3, k1, acc[3][1]);
                    acc[3][2] = f2fma(q3, k2, acc[3][2]); acc[3][3] = f2fma(q3, k3, acc[3][3]);
                }
            }

            const float sclf = 1.0f / 64.0f;
            #pragma unroll
            for (int p = 0; p < 4; p++) {
                float2 v0 = f2unpk(acc[p][0]), v1 = f2unpk(acc[p][1]);
                float2 v2 = f2unpk(acc[p][2]), v3 = f2unpk(acc[p][3]);
                int r = ty * 8 + 2 * p;
                float4 lo = make_float4(v0.x * sclf, v1.x * sclf, v2.x * sclf, v3.x * sclf);
                float4 hi = make_float4(v0.y * sclf, v1.y * sclf, v2.y * sclf, v3.y * sclf);
                *(float4*)&sc[r * SC_LD + tch * 512 + tx * 4] = lo;
                *(float4*)&sc[(r + 1) * SC_LD + tch * 512 + tx * 4] = hi;
            }
        }
        __syncthreads();

        // ---------------- softmax (8 warps x 2 rows) ----------------
        for (int rr = w; rr < 16; rr += 8) {
            float* row = &sc[rr * SC_LD];
            float m = -1e30f;
            for (int j = lane; j < 1024; j += 32) m = fmaxf(m, row[j]);
            #pragma unroll
            for (int o = 16; o > 0; o >>= 1) m = fmaxf(m, __shfl_xor_sync(0xffffffffu, m, o));
            float s = 0.0f;
            for (int j = lane; j < 1024; j += 32) {
                float e = __expf(row[j] - m);
                row[j] = e;
                s += e;
            }
            #pragma unroll
            for (int o = 16; o > 0; o >>= 1) s += __shfl_xor_sync(0xffffffffu, s, o);
            float inv = 1.0f / s;
            for (int j = lane; j < 1024; j += 32) row[j] *= inv;
        }
        __syncthreads();

        // ---------------- ave accumulation ----------------
        #pragma unroll
        for (int i = 0; i < 16; i++) {
            int m = i * 1024 + tid * 4;
            int r = m >> 10, c = m & 1023;
            float4 sv = *(float4*)&sc[r * SC_LD + c];
            float4 a = *(float4*)&av[m];
            a.x += 0.125f * sv.x; a.y += 0.125f * sv.y;
            a.z += 0.125f * sv.z; a.w += 0.125f * sv.w;
            *(float4*)&av[m] = a;
        }

        // ---------------- PV ----------------
        ull pacc[4][4];
        #pragma unroll
        for (int i = 0; i < 4; i++)
            #pragma unroll
            for (int p = 0; p < 4; p++) pacc[i][p] = 0ULL;

        for (int tc = 0; tc < 4; tc++) {
            __syncthreads();
            #pragma unroll
            for (int i = 0; i < 16; i++) {
                int e = i * 1024 + tid * 4;
                int t = e >> 6, dq = e & 63;
                *(float4*)&kv[t * 68 + dq] =
                    *(const float4*)&g_vt[b][tc * 256 + t][h * HD + dq];
            }
            __syncthreads();
            #pragma unroll
            for (int it = 0; it < 16; it++) {
                int t0 = w * 32 + 2 * it;
                int col = tc * 256 + t0;
                ull va[4], vb[4];
                #pragma unroll
                for (int p = 0; p < 4; p++) {
                    va[p] = *(ull*)&kv[t0 * 68 + d_l + 2 * p];
                    vb[p] = *(ull*)&kv[(t0 + 1) * 68 + d_l + 2 * p];
                }
                #pragma unroll
                for (int i = 0; i < 4; i++) {
                    float2 s2 = *(float2*)&sc[(r_l + i) * SC_LD + col];
                    ull a0 = f2dup(s2.x), a1 = f2dup(s2.y);
                    #pragma unroll
                    for (int p = 0; p < 4; p++) {
                        pacc[i][p] = f2fma(a0, va[p], pacc[i][p]);
                        pacc[i][p] = f2fma(a1, vb[p], pacc[i][p]);
                    }
                }
            }
        }

        // stage partials (reuse sc region) + cross-warp reduce
        __syncthreads();
        float* stg = sc;
        #pragma unroll
        for (int i = 0; i < 4; i++)
            #pragma unroll
            for (int p = 0; p < 4; p++)
                *(ull*)&stg[w * 1024 + (r_l + i) * 64 + d_l + 2 * p] = pacc[i][p];
        __syncthreads();
        {
            int o = tid * 4;
            float4 racc = make_float4(0.f, 0.f, 0.f, 0.f);
            #pragma unroll
            for (int ww = 0; ww < 8; ww++) {
                float4 v = *(float4*)&stg[ww * 1024 + o];
                racc.x += v.x; racc.y += v.y; racc.z += v.z; racc.w += v.w;
            }
            int r = o >> 6, dq = o & 63;
            *(float4*)&g_o1[b][s0 + r][h * HD + dq] = racc;
        }
    }

    // ---------------- write ave ----------------
    __syncthreads();
    #pragma unroll
    for (int i = 0; i < 16; i++) {
        int m = i * 1024 + tid * 4;
        int r = m >> 10, c = m & 1023;
        *(float4*)&ave[((size_t)b * SS + s0 + r) * SS + c] = *(float4*)&av[m];
    }
}

// ---------------------------------------------------------------------------
// Kernel 5: output projection: out = O1 @ Wo^T + bo  (double-buffered)
// ---------------------------------------------------------------------------
__global__ __launch_bounds__(256) void proj_kernel(const float* __restrict__ Wo,
                                                   const float* __restrict__ bo,
                                                   float* __restrict__ out) {
    __shared__ float As[2][8][128];
    __shared__ float Bs[2][8][128];
    const int m0 = blockIdx.x * 128, n0 = blockIdx.y * 128;
    const float* A = &g_o1[0][0][0];
    const int tid = threadIdx.x, tx = tid & 15, ty = tid >> 4;
    const int li = tid >> 1, lj = (tid & 1) * 4;

    ull acc[8][4];
    #pragma unroll
    for (int i = 0; i < 8; i++)
        #pragma unroll
        for (int p = 0; p < 4; p++) acc[i][p] = 0ULL;

    float4 avr, bvr;
    {
        avr = *(const float4*)&A[(size_t)(m0 + li) * DD + lj];
        bvr = *(const float4*)&Wo[(size_t)(n0 + li) * DD + lj];
        As[0][lj + 0][li] = avr.x; As[0][lj + 1][li] = avr.y;
        As[0][lj + 2][li] = avr.z; As[0][lj + 3][li] = avr.w;
        Bs[0][lj + 0][li] = bvr.x; Bs[0][lj + 1][li] = bvr.y;
        Bs[0][lj + 2][li] = bvr.z; Bs[0][lj + 3][li] = bvr.w;
    }
    __syncthreads();

    int cur = 0;
    for (int k0 = 0; k0 < DD; k0 += 8) {
        bool hn = (k0 + 8) < DD;
        if (hn) {
            avr = *(const float4*)&A[(size_t)(m0 + li) * DD + k0 + 8 + lj];
            bvr = *(const float4*)&Wo[(size_t)(n0 + li) * DD + k0 + 8 + lj];
        }

        #pragma unroll
        for (int j = 0; j < 8; j++) {
            float4 a0 = *(float4*)&As[cur][j][ty * 8];
            float4 a1 = *(float4*)&As[cur][j][ty * 8 + 4];
            ull b2[4];
            #pragma unroll
            for (int p = 0; p < 4; p++) b2[p] = *(ull*)&Bs[cur][j][tx * 8 + 2 * p];
            float avv[8] = {a0.x, a0.y, a0.z, a0.w, a1.x, a1.y, a1.z, a1.w};
            #pragma unroll
            for (int i = 0; i < 8; i++) {
                ull ad = f2dup(avv[i]);
                #pragma unroll
                for (int p = 0; p < 4; p++) acc[i][p] = f2fma(ad, b2[p], acc[i][p]);
            }
        }

        if (hn) {
            int nb = cur ^ 1;
            As[nb][lj + 0][li] = avr.x; As[nb][lj + 1][li] = avr.y;
            As[nb][lj + 2][li] = avr.z; As[nb][lj + 3][li] = avr.w;
            Bs[nb][lj + 0][li] = bvr.x; Bs[nb][lj + 1][li] = bvr.y;
            Bs[nb][lj + 2][li] = bvr.z; Bs[nb][lj + 3][li] = bvr.w;
        }
        __syncthreads();
        cur ^= 1;
    }

    #pragma unroll
    for (int i = 0; i < 8; i++) {
        int m = m0 + ty * 8 + i;
        #pragma unroll
        for (int p = 0; p < 4; p++) {
            ull bb = *(const ull*)&bo[n0 + tx * 8 + 2 * p];
            ull r = f2add(acc[i][p], bb);
            *(ull*)&out[(size_t)m * DD + n0 + tx * 8 + 2 * p] = r;
        }
    }
}

// ---------------------------------------------------------------------------
extern "C" void kernel_launch(void* const* d_in, const int* in_sizes, int n_in,
                              void* d_out, int out_size) {
    const float* query = (const float*)d_in[0];
    const float* key_t = (const float*)d_in[1];
    const float* value = (const float*)d_in[2];
    const float* Wq    = (const float*)d_in[3];
    const float* bq    = (const float*)d_in[4];
    const float* Wk    = (const float*)d_in[5];
    const float* bk    = (const float*)d_in[6];
    const float* Wv    = (const float*)d_in[7];
    const float* bv    = (const float*)d_in[8];
    const float* Wo    = (const float*)d_in[9];
    const float* bo    = (const float*)d_in[10];

    float* out = (float*)d_out;
    float* ave = out + (size_t)BB * SS * DD;

    const int FA_SMEM = (16 * SC_LD + 16 * 1024 + 17408 + 1024) * (int)sizeof(float);
    cudaFuncSetAttribute(fused_attn, cudaFuncAttributeMaxDynamicSharedMemorySize, FA_SMEM);

    transpose_kernel<<<dim3(SS / 32, DD / 32, 3 * BB), dim3(32, 8)>>>(query, key_t, value);
    conv_kernel<<<dim3(DD / 128, SS / 128, 3 * BB), 256>>>(Wq, bq, Wk, bk, Wv, bv);
    vt_kernel<<<dim3(SS / 32, DD / 32, BB), dim3(32, 8)>>>();
    fused_attn<<<dim3(SS / 16, BB), 256, FA_SMEM>>>(ave);
    proj_kernel<<<dim3((BB * SS) / 128, DD / 128), 256>>>(Wo, bo, out);
}

// round 4
// speedup vs baseline: 1.3100x; 1.3100x over previous
#include <cuda_runtime.h>
#include <cuda_bf16.h>
#include <cstdint>

// ---------------------------------------------------------------------------
// ConvMultiheadAttention: B=8, S=1024, D=512, H=8, hd=64, KERNEL=3
// out  = [8,1024,512]  ; ave = [8,1024,1024]
// ---------------------------------------------------------------------------

#define BB 8
#define SS 1024
#define DD 512
#define HH 8
#define HD 64

typedef unsigned long long ull;

// ----- f32x2 helpers --------------------------------------------------------
__device__ __forceinline__ ull f2fma(ull a, ull b, ull c) {
    ull d; asm("fma.rn.f32x2 %0, %1, %2, %3;" : "=l"(d) : "l"(a), "l"(b), "l"(c)); return d;
}
__device__ __forceinline__ ull f2dup(float x) {
    ull d; asm("mov.b64 %0, {%1, %1};" : "=l"(d) : "f"(x)); return d;
}
__device__ __forceinline__ ull f2add(ull a, ull b) {
    ull d; asm("add.rn.f32x2 %0, %1, %2;" : "=l"(d) : "l"(a), "l"(b)); return d;
}
__device__ __forceinline__ float2 f2unpk(ull a) {
    float2 r; asm("mov.b64 {%0, %1}, %2;" : "=f"(r.x), "=f"(r.y) : "l"(a)); return r;
}

// ----- tf32 helpers ---------------------------------------------------------
__device__ __forceinline__ float to_tf32(float x) {
    float r; asm("cvt.rna.tf32.f32 %0, %1;" : "=f"(r) : "f"(x)); return r;
}
__device__ __forceinline__ void mma_tf32(float4& d, const uint32_t a[4],
                                         const uint32_t b[2]) {
    asm("mma.sync.aligned.m16n8k8.row.col.f32.tf32.tf32.f32 "
        "{%0,%1,%2,%3}, {%4,%5,%6,%7}, {%8,%9}, {%0,%1,%2,%3};"
        : "+f"(d.x), "+f"(d.y), "+f"(d.z), "+f"(d.w)
        : "r"(a[0]), "r"(a[1]), "r"(a[2]), "r"(a[3]), "r"(b[0]), "r"(b[1]));
}

// ----- scratch (static device globals) --------------------------------------
__device__ float g_xt[3][BB][DD][SS];    // transposed inputs  [B,D,S]
__device__ float g_qkv[3][BB][DD][SS];   // conv outputs Q,K,V [B,D,S]
__device__ float g_vt[BB][SS][DD];       // V transposed to [B,S,D]
__device__ float g_p[(size_t)BB * HH * SS * SS]; // attention probs
__device__ float g_o1[BB][SS][DD];       // pre-projection output

// ---------------------------------------------------------------------------
// Kernel 1: transpose [B,S,D] -> [B,D,S] for q, k, v
// ---------------------------------------------------------------------------
__global__ void transpose_kernel(const float* __restrict__ q,
                                 const float* __restrict__ k,
                                 const float* __restrict__ v) {
    __shared__ float tile[32][33];
    int zz = blockIdx.z;
    int tn = zz / BB, b = zz % BB;
    const float* src = (tn == 0) ? q : (tn == 1) ? k : v;
    float* dst = &g_xt[tn][b][0][0];
    int s0 = blockIdx.x * 32, d0 = blockIdx.y * 32;
    int tx = threadIdx.x, ty = threadIdx.y;
    #pragma unroll
    for (int i = ty; i < 32; i += 8)
        tile[i][tx] = src[((size_t)b * SS + s0 + i) * DD + d0 + tx];
    __syncthreads();
    #pragma unroll
    for (int i = ty; i < 32; i += 8)
        dst[(size_t)(d0 + i) * SS + s0 + tx] = tile[tx][i];
}

// ---------------------------------------------------------------------------
// Kernel 2: conv1d projections via mma.sync tf32 (split-precision, 3 terms).
// C[co 128][s 128] = sum_kk A[co][kk] * B[kk][s], im2col B on the fly.
// Block 128x128, 8 warps (2m x 4n of 64x32 warp tiles), k-slab 16, dbl-buf.
// A = Ah + Al, B = Bh + Bl (tf32 splits); D += AhBh + AhBl + AlBh.
// ---------------------------------------------------------------------------
#define CAH 20      // A smem row stride (floats)
#define CBH 136     // B smem row stride (floats)
#define CV_AH 0
#define CV_AL 2560
#define CV_BH 5120
#define CV_BL 7296
#define CV_BUF_FLOATS 9472
#define CV_SMEM (2 * CV_BUF_FLOATS * (int)sizeof(float))

__global__ __launch_bounds__(256, 1)
void conv_mma(const float* __restrict__ Wq, const float* __restrict__ bq,
              const float* __restrict__ Wk, const float* __restrict__ bk,
              const float* __restrict__ Wv, const float* __restrict__ bv) {
    extern __shared__ float sm[];
    __shared__ float s_bias[128];

    const int zz = blockIdx.z, tn = zz / BB, b = zz % BB;
    const float* W    = (tn == 0) ? Wq : (tn == 1) ? Wk : Wv;
    const float* bias = (tn == 0) ? bq : (tn == 1) ? bk : bv;
    const int KER  = (tn == 2) ? 1 : 3;
    const int Kdim = DD * KER;
    const float* xsrc = &g_xt[tn][b][0][0];
    float* out = &g_qkv[tn][b][0][0];
    const int m0 = blockIdx.x * 128, n0 = blockIdx.y * 128;
    const int tid = threadIdx.x, wid = tid >> 5, lane = tid & 31;
    const int g = lane >> 2, tg = lane & 3;
    const int wm = (wid >> 2) * 64, wn = (wid & 3) * 32;

    if (tid < 128) s_bias[tid] = bias[m0 + tid];

    float4 dacc[4][4];
    #pragma unroll
    for (int mi = 0; mi < 4; mi++)
        #pragma unroll
        for (int ni = 0; ni < 4; ni++) dacc[mi][ni] = make_float4(0.f, 0.f, 0.f, 0.f);

    // thread mapping for global->smem staging
    const int la_row = tid >> 2, la_k = (tid & 3) * 4;   // A: 64 rows per pass, 2 passes
    const int lb_k = tid >> 4, lb_s = tid & 15;          // B: 16 k-rows, 8 s each (stride 16)

    const int NC = Kdim / 16;
    float4 a_reg[2];
    float  b_reg[8];

    // ---- prologue: load slab 0 ----
    #pragma unroll
    for (int rr = 0; rr < 2; rr++)
        a_reg[rr] = *(const float4*)&W[(size_t)(m0 + rr * 64 + la_row) * Kdim + la_k];
    {
        int kk = lb_k;
        int ci, kof;
        if (KER == 3) { ci = kk / 3; kof = kk - ci * 3 - 1; }
        else          { ci = kk;     kof = 0; }
        const float* xr = xsrc + (size_t)ci * SS;
        #pragma unroll
        for (int j = 0; j < 8; j++) {
            int s = n0 + lb_s + 16 * j + kof;
            b_reg[j] = (s >= 0 && s < SS) ? xr[s] : 0.0f;
        }
    }
    // store slab 0 into buffer 0
    {
        float* Ah = sm + CV_AH; float* Al = sm + CV_AL;
        float* Bh = sm + CV_BH; float* Bl = sm + CV_BL;
        #pragma unroll
        for (int rr = 0; rr < 2; rr++) {
            int row = rr * 64 + la_row;
            float h0 = to_tf32(a_reg[rr].x), h1 = to_tf32(a_reg[rr].y);
            float h2 = to_tf32(a_reg[rr].z), h3 = to_tf32(a_reg[rr].w);
            *(float4*)&Ah[row * CAH + la_k] = make_float4(h0, h1, h2, h3);
            *(float4*)&Al[row * CAH + la_k] =
                make_float4(to_tf32(a_reg[rr].x - h0), to_tf32(a_reg[rr].y - h1),
                            to_tf32(a_reg[rr].z - h2), to_tf32(a_reg[rr].w - h3));
        }
        #pragma unroll
        for (int j = 0; j < 8; j++) {
            float h = to_tf32(b_reg[j]);
            Bh[lb_k * CBH + lb_s + 16 * j] = h;
            Bl[lb_k * CBH + lb_s + 16 * j] = to_tf32(b_reg[j] - h);
        }
    }
    __syncthreads();

    for (int c = 0; c < NC; c++) {
        const int bf = c & 1;
        const bool have = (c + 1) < NC;

        // ---- issue global loads for slab c+1 ----
        if (have) {
            #pragma unroll
            for (int rr = 0; rr < 2; rr++)
                a_reg[rr] = *(const float4*)&W[(size_t)(m0 + rr * 64 + la_row) * Kdim
                                               + (c + 1) * 16 + la_k];
            int kk = (c + 1) * 16 + lb_k;
            int ci, kof;
            if (KER == 3) { ci = kk / 3; kof = kk - ci * 3 - 1; }
            else          { ci = kk;     kof = 0; }
            const float* xr = xsrc + (size_t)ci * SS;
            #pragma unroll
            for (int j = 0; j < 8; j++) {
                int s = n0 + lb_s + 16 * j + kof;
                b_reg[j] = (s >= 0 && s < SS) ? xr[s] : 0.0f;
            }
        }

        // ---- compute on buffer bf ----
        const float* Ah = sm + bf * CV_BUF_FLOATS + CV_AH;
        const float* Al = sm + bf * CV_BUF_FLOATS + CV_AL;
        const float* Bh = sm + bf * CV_BUF_FLOATS + CV_BH;
        const float* Bl = sm + bf * CV_BUF_FLOATS + CV_BL;

        #pragma unroll
        for (int ks = 0; ks < 16; ks += 8) {
            uint32_t ah[4][4], al[4][4], bh[4][2], bl[4][2];
            #pragma unroll
            for (int mi = 0; mi < 4; mi++) {
                int r0 = (wm + mi * 16 + g) * CAH + ks + tg;
                int r1 = r0 + 8 * CAH;
                ah[mi][0] = __float_as_uint(Ah[r0]);
                ah[mi][1] = __float_as_uint(Ah[r1]);
                ah[mi][2] = __float_as_uint(Ah[r0 + 4]);
                ah[mi][3] = __float_as_uint(Ah[r1 + 4]);
                al[mi][0] = __float_as_uint(Al[r0]);
                al[mi][1] = __float_as_uint(Al[r1]);
                al[mi][2] = __float_as_uint(Al[r0 + 4]);
                al[mi][3] = __float_as_uint(Al[r1 + 4]);
            }
            #pragma unroll
            for (int ni = 0; ni < 4; ni++) {
                int c0 = (ks + tg) * CBH + wn + ni * 8 + g;
                int c1 = c0 + 4 * CBH;
                bh[ni][0] = __float_as_uint(Bh[c0]);
                bh[ni][1] = __float_as_uint(Bh[c1]);
                bl[ni][0] = __float_as_uint(Bl[c0]);
                bl[ni][1] = __float_as_uint(Bl[c1]);
            }
            #pragma unroll
            for (int mi = 0; mi < 4; mi++)
                #pragma unroll
                for (int ni = 0; ni < 4; ni++) {
                    mma_tf32(dacc[mi][ni], ah[mi], bh[ni]);
                    mma_tf32(dacc[mi][ni], ah[mi], bl[ni]);
                    mma_tf32(dacc[mi][ni], al[mi], bh[ni]);
                }
        }

        // ---- store slab c+1 into buffer bf^1 ----
        if (have) {
            float* Ah2 = sm + (bf ^ 1) * CV_BUF_FLOATS + CV_AH;
            float* Al2 = sm + (bf ^ 1) * CV_BUF_FLOATS + CV_AL;
            float* Bh2 = sm + (bf ^ 1) * CV_BUF_FLOATS + CV_BH;
            float* Bl2 = sm + (bf ^ 1) * CV_BUF_FLOATS + CV_BL;
            #pragma unroll
            for (int rr = 0; rr < 2; rr++) {
                int row = rr * 64 + la_row;
                float h0 = to_tf32(a_reg[rr].x), h1 = to_tf32(a_reg[rr].y);
                float h2 = to_tf32(a_reg[rr].z), h3 = to_tf32(a_reg[rr].w);
                *(float4*)&Ah2[row * CAH + la_k] = make_float4(h0, h1, h2, h3);
                *(float4*)&Al2[row * CAH + la_k] =
                    make_float4(to_tf32(a_reg[rr].x - h0), to_tf32(a_reg[rr].y - h1),
                                to_tf32(a_reg[rr].z - h2), to_tf32(a_reg[rr].w - h3));
            }
            #pragma unroll
            for (int j = 0; j < 8; j++) {
                float h = to_tf32(b_reg[j]);
                Bh2[lb_k * CBH + lb_s + 16 * j] = h;
                Bl2[lb_k * CBH + lb_s + 16 * j] = to_tf32(b_reg[j] - h);
            }
        }
        __syncthreads();
    }

    // ---- epilogue: add bias, write [co][s] ----
    #pragma unroll
    for (int mi = 0; mi < 4; mi++) {
        int lr0 = wm + mi * 16 + g;
        float b0 = s_bias[lr0], b1 = s_bias[lr0 + 8];
        #pragma unroll
        for (int ni = 0; ni < 4; ni++) {
            int col = n0 + wn + ni * 8 + 2 * tg;
            float4 d = dacc[mi][ni];
            *(float2*)&out[(size_t)(m0 + lr0) * SS + col]     = make_float2(d.x + b0, d.y + b0);
            *(float2*)&out[(size_t)(m0 + lr0 + 8) * SS + col] = make_float2(d.z + b1, d.w + b1);
        }
    }
}

// ---------------------------------------------------------------------------
// Kernel 3: transpose V conv output [B,D,S] -> [B,S,D]
// ---------------------------------------------------------------------------
__global__ void vt_kernel() {
    __shared__ float tile[32][33];
    int b = blockIdx.z;
    const float* src = &g_qkv[2][b][0][0];
    float* dst = &g_vt[b][0][0];
    int s0 = blockIdx.x * 32, d0 = blockIdx.y * 32;
    int tx = threadIdx.x, ty = threadIdx.y;
    #pragma unroll
    for (int i = ty; i < 32; i += 8)
        tile[i][tx] = src[(size_t)(d0 + i) * SS + s0 + tx];
    __syncthreads();
    #pragma unroll
    for (int i = ty; i < 32; i += 8)
        dst[(size_t)(s0 + i) * DD + d0 + tx] = tile[tx][i];
}

// ---------------------------------------------------------------------------
// Kernel 4: scores + softmax per (b, h, 32-row tile)
// ---------------------------------------------------------------------------
__global__ __launch_bounds__(256) void scores_kernel() {
    extern __shared__ float sm[];
    float* sc = sm;                    // 32*1024
    float* Kc = sm + 32 * 1024;        // 64*256
    float* Qt = sm + 32 * 1024 + 64 * 256; // 64*32

    const int b = blockIdx.z, h = blockIdx.y, s0 = blockIdx.x * 32;
    const float* Qg = &g_qkv[0][b][h * HD][0];
    const float* Kg = &g_qkv[1][b][h * HD][0];
    const int tid = threadIdx.x;

    #pragma unroll
    for (int i = 0; i < 2; i++) {
        int e = i * 1024 + tid * 4;
        int d = e >> 5, r = e & 31;
        *(float4*)&Qt[d * 32 + r] = *(const float4*)&Qg[(size_t)d * SS + s0 + r];
    }

    const int tx = tid & 63, ty = tid >> 6;
    const int t_l = tx * 4, r_l = ty * 8;

    for (int tc = 0; tc < 4; tc++) {
        __syncthreads();
        #pragma unroll
        for (int i = 0; i < 16; i++) {
            int e = i * 1024 + tid * 4;
            int d = e >> 8, t = e & 255;
            *(float4*)&Kc[d * 256 + t] = *(const float4*)&Kg[(size_t)d * SS + tc * 256 + t];
        }
        __syncthreads();

        ull acc[4][4];
        #pragma unroll
        for (int ri = 0; ri < 4; ri++)
            #pragma unroll
            for (int j = 0; j < 4; j++) acc[ri][j] = 0ULL;

        #pragma unroll
        for (int d = 0; d < 64; d++) {
            const float* qr = &Qt[d * 32 + r_l];
            ull q0 = *(ull*)&qr[0], q1 = *(ull*)&qr[2];
            ull q2 = *(ull*)&qr[4], q3 = *(ull*)&qr[6];
            float4 kv = *(float4*)&Kc[d * 256 + t_l];
            ull k0 = f2dup(kv.x), k1 = f2dup(kv.y);
            ull k2 = f2dup(kv.z), k3 = f2dup(kv.w);
            acc[0][0] = f2fma(q0, k0, acc[0][0]); acc[0][1] = f2fma(q0, k1, acc[0][1]);
            acc[0][2] = f2fma(q0, k2, acc[0][2]); acc[0][3] = f2fma(q0, k3, acc[0][3]);
            acc[1][0] = f2fma(q1, k0, acc[1][0]); acc[1][1] = f2fma(q1, k1, acc[1][1]);
            acc[1][2] = f2fma(q1, k2, acc[1][2]); acc[1][3] = f2fma(q1, k3, acc[1][3]);
            acc[2][0] = f2fma(q2, k0, acc[2][0]); acc[2][1] = f2fma(q2, k1, acc[2][1]);
            acc[2][2] = f2fma(q2, k2, acc[2][2]); acc[2][3] = f2fma(q2, k3, acc[2][3]);
            acc[3][0] = f2fma(q3, k0, acc[3][0]); acc[3][1] = f2fma(q3, k1, acc[3][1]);
            acc[3][2] = f2fma(q3, k2, acc[3][2]); acc[3][3] = f2fma(q3, k3, acc[3][3]);
        }

        const float sclf = 1.0f / 64.0f;
        #pragma unroll
        for (int ri = 0; ri < 4; ri++)
            #pragma unroll
            for (int j = 0; j < 4; j++) {
                float2 v = f2unpk(acc[ri][j]);
                sc[(r_l + 2 * ri) * 1024 + tc * 256 + t_l + j]     = v.x * sclf;
                sc[(r_l + 2 * ri + 1) * 1024 + tc * 256 + t_l + j] = v.y * sclf;
            }
    }
    __syncthreads();

    const int warp = tid >> 5, lane = tid & 31;
    for (int rr = warp; rr < 32; rr += 8) {
        float* row = &sc[rr * 1024];
        float m = -1e30f;
        for (int j = lane; j < 1024; j += 32) m = fmaxf(m, row[j]);
        #pragma unroll
        for (int o = 16; o > 0; o >>= 1) m = fmaxf(m, __shfl_xor_sync(0xffffffffu, m, o));
        float s = 0.0f;
        for (int j = lane; j < 1024; j += 32) {
            float e = __expf(row[j] - m);
            row[j] = e;
            s += e;
        }
        #pragma unroll
        for (int o = 16; o > 0; o >>= 1) s += __shfl_xor_sync(0xffffffffu, s, o);
        float inv = 1.0f / s;
        for (int j = lane; j < 1024; j += 32) row[j] *= inv;
    }
    __syncthreads();

    float* Pg = &g_p[(((size_t)(b * HH + h)) << 20) + (size_t)s0 * SS];
    #pragma unroll
    for (int i = 0; i < 32; i++) {
        int e = i * 1024 + tid * 4;
        *(float4*)&Pg[e] = *(float4*)&sc[e];
    }
}

// ---------------------------------------------------------------------------
// Kernel 5: ave_att = mean over heads of P
// ---------------------------------------------------------------------------
__global__ void ave_kernel(float* __restrict__ ave) {
    size_t idx = (size_t)blockIdx.x * 256 + threadIdx.x;
    size_t e = idx * 4;
    size_t b = e >> 20, st = e & 1048575;
    float4 a = make_float4(0.f, 0.f, 0.f, 0.f);
    #pragma unroll
    for (int h = 0; h < HH; h++) {
        const float4 p = *(const float4*)&g_p[((b * HH + h) << 20) + st];
        a.x += p.x; a.y += p.y; a.z += p.z; a.w += p.w;
    }
    a.x *= 0.125f; a.y *= 0.125f; a.z *= 0.125f; a.w *= 0.125f;
    *(float4*)&ave[e] = a;
}

// ---------------------------------------------------------------------------
// Kernel 6: PV GEMM per (b,h) with transposed V, f32x2 pairs along d.
// Tile 128(r) x 64(d) x 32(t).  micro: 4r x 8d per thread.
// ---------------------------------------------------------------------------
__global__ __launch_bounds__(256) void pv_kernel() {
    __shared__ float Ps[128 * 36];   // [r][t], stride 36
    __shared__ float Vs[32 * 64];    // [t][d], stride 64
    const int b = blockIdx.z, h = blockIdx.y, s0 = blockIdx.x * 128;
    const float* Pg = &g_p[((size_t)(b * HH + h)) << 20];
    const int tid = threadIdx.x;
    const int tx = tid & 7, ty = tid >> 3;
    const int d_l = tx * 8, r_l = ty * 4;

    ull acc[4][4];
    #pragma unroll
    for (int i = 0; i < 4; i++)
        #pragma unroll
        for (int p = 0; p < 4; p++) acc[i][p] = 0ULL;

    const int pr = tid >> 1, pt = (tid & 1) * 16;
    for (int t0 = 0; t0 < SS; t0 += 32) {
        __syncthreads();
        #pragma unroll
        for (int j = 0; j < 4; j++)
            *(float4*)&Ps[pr * 36 + pt + j * 4] =
                *(const float4*)&Pg[(size_t)(s0 + pr) * SS + t0 + pt + j * 4];
        #pragma unroll
        for (int j = 0; j < 2; j++) {
            int idx = j * 256 + tid;
            int t = idx >> 4, d4 = (idx & 15) * 4;
            *(float4*)&Vs[t * 64 + d4] = *(const float4*)&g_vt[b][t0 + t][h * HD + d4];
        }
        __syncthreads();

        #pragma unroll
        for (int t = 0; t < 32; t++) {
            ull vb[4];
            #pragma unroll
            for (int p = 0; p < 4; p++) vb[p] = *(ull*)&Vs[t * 64 + d_l + 2 * p];
            #pragma unroll
            for (int i = 0; i < 4; i++) {
                ull ad = f2dup(Ps[(r_l + i) * 36 + t]);
                #pragma unroll
                for (int p = 0; p < 4; p++) acc[i][p] = f2fma(ad, vb[p], acc[i][p]);
            }
        }
    }

    #pragma unroll
    for (int i = 0; i < 4; i++)
        #pragma unroll
        for (int p = 0; p < 4; p++)
            *(ull*)&g_o1[b][s0 + r_l + i][h * HD + d_l + 2 * p] = acc[i][p];
}

// ---------------------------------------------------------------------------
// Kernel 7: output projection: out = O1 @ Wo^T + bo  (double-buffered f32x2)
// ---------------------------------------------------------------------------
__global__ __launch_bounds__(256) void proj_kernel(const float* __restrict__ Wo,
                                                   const float* __restrict__ bo,
                                                   float* __restrict__ out) {
    __shared__ float As[2][8][128];
    __shared__ float Bs[2][8][128];
    const int m0 = blockIdx.x * 128, n0 = blockIdx.y * 128;
    const float* A = &g_o1[0][0][0];
    const int tid = threadIdx.x, tx = tid & 15, ty = tid >> 4;
    const int li = tid >> 1, lj = (tid & 1) * 4;

    ull acc[8][4];
    #pragma unroll
    for (int i = 0; i < 8; i++)
        #pragma unroll
        for (int p = 0; p < 4; p++) acc[i][p] = 0ULL;

    float4 avr, bvr;
    {
        avr = *(const float4*)&A[(size_t)(m0 + li) * DD + lj];
        bvr = *(const float4*)&Wo[(size_t)(n0 + li) * DD + lj];
        As[0][lj + 0][li] = avr.x; As[0][lj + 1][li] = avr.y;
        As[0][lj + 2][li] = avr.z; As[0][lj + 3][li] = avr.w;
        Bs[0][lj + 0][li] = bvr.x; Bs[0][lj + 1][li] = bvr.y;
        Bs[0][lj + 2][li] = bvr.z; Bs[0][lj + 3][li] = bvr.w;
    }
    __syncthreads();

    int cur = 0;
    for (int k0 = 0; k0 < DD; k0 += 8) {
        bool hn = (k0 + 8) < DD;
        if (hn) {
            avr = *(const float4*)&A[(size_t)(m0 + li) * DD + k0 + 8 + lj];
            bvr = *(const float4*)&Wo[(size_t)(n0 + li) * DD + k0 + 8 + lj];
        }

        #pragma unroll
        for (int j = 0; j < 8; j++) {
            float4 a0 = *(float4*)&As[cur][j][ty * 8];
            float4 a1 = *(float4*)&As[cur][j][ty * 8 + 4];
            ull b2[4];
            #pragma unroll
            for (int p = 0; p < 4; p++) b2[p] = *(ull*)&Bs[cur][j][tx * 8 + 2 * p];
            float avv[8] = {a0.x, a0.y, a0.z, a0.w, a1.x, a1.y, a1.z, a1.w};
            #pragma unroll
            for (int i = 0; i < 8; i++) {
                ull ad = f2dup(avv[i]);
                #pragma unroll
                for (int p = 0; p < 4; p++) acc[i][p] = f2fma(ad, b2[p], acc[i][p]);
            }
        }

        if (hn) {
            int nb = cur ^ 1;
            As[nb][lj + 0][li] = avr.x; As[nb][lj + 1][li] = avr.y;
            As[nb][lj + 2][li] = avr.z; As[nb][lj + 3][li] = avr.w;
            Bs[nb][lj + 0][li] = bvr.x; Bs[nb][lj + 1][li] = bvr.y;
            Bs[nb][lj + 2][li] = bvr.z; Bs[nb][lj + 3][li] = bvr.w;
        }
        __syncthreads();
        cur ^= 1;
    }

    #pragma unroll
    for (int i = 0; i < 8; i++) {
        int m = m0 + ty * 8 + i;
        #pragma unroll
        for (int p = 0; p < 4; p++) {
            ull bb = *(const ull*)&bo[n0 + tx * 8 + 2 * p];
            ull r = f2add(acc[i][p], bb);
            *(ull*)&out[(size_t)m * DD + n0 + tx * 8 + 2 * p] = r;
        }
    }
}

// ---------------------------------------------------------------------------
extern "C" void kernel_launch(void* const* d_in, const int* in_sizes, int n_in,
                              void* d_out, int out_size) {
    const float* query = (const float*)d_in[0];
    const float* key_t = (const float*)d_in[1];
    const float* value = (const float*)d_in[2];
    const float* Wq    = (const float*)d_in[3];
    const float* bq    = (const float*)d_in[4];
    const float* Wk    = (const float*)d_in[5];
    const float* bk    = (const float*)d_in[6];
    const float* Wv    = (const float*)d_in[7];
    const float* bv    = (const float*)d_in[8];
    const float* Wo    = (const float*)d_in[9];
    const float* bo    = (const float*)d_in[10];

    float* out = (float*)d_out;
    float* ave = out + (size_t)BB * SS * DD;

    const size_t SC_SMEM = (size_t)(32 * 1024 + 64 * 256 + 64 * 32) * sizeof(float);
    cudaFuncSetAttribute(scores_kernel, cudaFuncAttributeMaxDynamicSharedMemorySize,
                         (int)SC_SMEM);
    cudaFuncSetAttribute(conv_mma, cudaFuncAttributeMaxDynamicSharedMemorySize, CV_SMEM);

    transpose_kernel<<<dim3(SS / 32, DD / 32, 3 * BB), dim3(32, 8)>>>(query, key_t, value);
    conv_mma<<<dim3(DD / 128, SS / 128, 3 * BB), 256, CV_SMEM>>>(Wq, bq, Wk, bk, Wv, bv);
    vt_kernel<<<dim3(SS / 32, DD / 32, BB), dim3(32, 8)>>>();
    scores_kernel<<<dim3(SS / 32, HH, BB), 256, SC_SMEM>>>();
    pv_kernel<<<dim3(SS / 128, HH, BB), 256>>>();
    ave_kernel<<<(BB * SS * SS / 4) / 256, 256>>>(ave);
    proj_kernel<<<dim3((BB * SS) / 128, DD / 128), 256>>>(Wo, bo, out);
}